// round 3
// baseline (speedup 1.0000x reference)
#include <cuda_runtime.h>
#include <math.h>

#define HH 768
#define SS 128
#define LL 10

// Scratch (no allocation allowed)
__device__ float g_h[2][SS * HH];         // h_src, h_tgt  (x@W + bias)
__device__ float g_u[2][SS * 20];         // u[s][r][l] = x @ A   (rl = r*10+l)
__device__ float g_ab[2][LL * SS * HH];   // a[l][s][i], b[l][t][i]

// ---------------------------------------------------------------------------
// Kernel 1: h = x @ W + bias   (two 128x768x768 fp32 GEMMs)
// grid (12 i-tiles of 64, 2 s-tiles of 64, 2 mats), 256 threads, 4x4/thread
// ---------------------------------------------------------------------------
__global__ void gemm_h_kernel(const float* __restrict__ x,
                              const float* __restrict__ Wsrc, const float* __restrict__ bsrc,
                              const float* __restrict__ Wtgt, const float* __restrict__ btgt) {
    const int mat = blockIdx.z;
    const float* __restrict__ Wm = mat ? Wtgt : Wsrc;
    const float* __restrict__ bm = mat ? btgt : bsrc;
    const int i0 = blockIdx.x * 64;
    const int s0 = blockIdx.y * 64;

    __shared__ float sX[16][64];   // [k][s]
    __shared__ float sW[16][64];   // [k][i]

    const int tid = threadIdx.x;
    const int tx = tid % 16;       // i direction
    const int ty = tid / 16;       // s direction

    float acc[4][4] = {};

    for (int k0 = 0; k0 < HH; k0 += 16) {
        #pragma unroll
        for (int e = tid; e < 64 * 16; e += 256) {
            int ssi = e >> 4, kk = e & 15;
            sX[kk][ssi] = x[(s0 + ssi) * HH + k0 + kk];
        }
        #pragma unroll
        for (int e = tid; e < 16 * 64; e += 256) {
            int kk = e >> 6, ii = e & 63;
            sW[kk][ii] = Wm[(k0 + kk) * HH + i0 + ii];
        }
        __syncthreads();
        #pragma unroll
        for (int kk = 0; kk < 16; kk++) {
            float4 a4 = *(const float4*)&sX[kk][ty * 4];
            float4 b4 = *(const float4*)&sW[kk][tx * 4];
            float av[4] = {a4.x, a4.y, a4.z, a4.w};
            float bv[4] = {b4.x, b4.y, b4.z, b4.w};
            #pragma unroll
            for (int i = 0; i < 4; i++)
                #pragma unroll
                for (int j = 0; j < 4; j++)
                    acc[i][j] = fmaf(av[i], bv[j], acc[i][j]);
        }
        __syncthreads();
    }
    #pragma unroll
    for (int i = 0; i < 4; i++)
        #pragma unroll
        for (int j = 0; j < 4; j++) {
            int s = s0 + ty * 4 + i;
            int ii = i0 + tx * 4 + j;
            g_h[mat][s * HH + ii] = acc[i][j] + bm[ii];
        }
}

// ---------------------------------------------------------------------------
// Kernel 2: u[s][r][l] = sum_h x[s,h] * A[h,r,l]    (tiny: 128x768x20 x2)
// grid 128 (one block per s), 64 threads (40 active dot products)
// ---------------------------------------------------------------------------
__global__ void calc_u_kernel(const float* __restrict__ x,
                              const float* __restrict__ Asrc,
                              const float* __restrict__ Atgt) {
    __shared__ float sx[HH];
    const int s = blockIdx.x;
    for (int e = threadIdx.x; e < HH; e += 64) sx[e] = x[s * HH + e];
    __syncthreads();
    const int j = threadIdx.x;
    if (j < 40) {
        const int mat = j / 20;
        const int rl  = j % 20;                 // r*10 + l, matches A (H,R,L) flatten
        const float* __restrict__ A = mat ? Atgt : Asrc;
        float acc = 0.f;
        #pragma unroll 8
        for (int h = 0; h < HH; h++) acc = fmaf(sx[h], A[h * 20 + rl], acc);
        g_u[mat][s * 20 + rl] = acc;
    }
}

// ---------------------------------------------------------------------------
// Kernel 3: a[l][s][i] = h[s][i] + u[s][0][l]*B[0][i][l] + u[s][1][l]*B[1][i][l]
// grid (8 s-chunks of 16, 10 l, 2 mats), 256 threads
// ---------------------------------------------------------------------------
__global__ void expand_ab_kernel(const float* __restrict__ Bsrc,
                                 const float* __restrict__ Btgt) {
    const int mat = blockIdx.z;
    const int l   = blockIdx.y;
    const int s0  = blockIdx.x * 16;
    const float* __restrict__ Bm = mat ? Btgt : Bsrc;

    __shared__ float sB0[HH];
    __shared__ float sB1[HH];
    __shared__ float su[16][2];

    for (int e = threadIdx.x; e < HH; e += 256) {
        sB0[e] = Bm[(0 * HH + e) * LL + l];
        sB1[e] = Bm[(1 * HH + e) * LL + l];
    }
    if (threadIdx.x < 32) {
        int si = threadIdx.x >> 1, r = threadIdx.x & 1;
        su[si][r] = g_u[mat][(s0 + si) * 20 + r * 10 + l];
    }
    __syncthreads();

    for (int e = threadIdx.x; e < 16 * HH; e += 256) {
        int si = e / HH, ii = e % HH;
        float v = g_h[mat][(s0 + si) * HH + ii]
                + su[si][0] * sB0[ii] + su[si][1] * sB1[ii];
        g_ab[mat][(l * SS + s0 + si) * HH + ii] = v;
    }
}

// ---------------------------------------------------------------------------
// Kernel 4 (main): out[l,s,t] = sum_i gelu(a[l,s,i] + b[l,t,i]) * c[i,l]
// 125.8M exact-erf gelu evals. grid (8,8,10) = 640 blocks, 256 threads,
// 16x16 (s,t) tile, i staged in smem in chunks of 64.
// Four independent accumulators to overlap the erff dependency chains.
// ---------------------------------------------------------------------------
__global__ void main_kernel(const float* __restrict__ cls,
                            float* __restrict__ out) {
    const int l  = blockIdx.z;
    const int s0 = blockIdx.y * 16;
    const int t0 = blockIdx.x * 16;
    const int tid = threadIdx.x;
    const int tx = tid % 16;   // t
    const int ty = tid / 16;   // s

    __shared__ float sA[16][65];   // pad 65: conflict-free strided reads
    __shared__ float sB[16][65];
    __shared__ float sC[64];

    const float* __restrict__ Abase = &g_ab[0][(l * SS + s0) * HH];
    const float* __restrict__ Bbase = &g_ab[1][(l * SS + t0) * HH];

    float acc0 = 0.f, acc1 = 0.f, acc2 = 0.f, acc3 = 0.f;

    for (int c0 = 0; c0 < HH; c0 += 64) {
        #pragma unroll
        for (int e = tid; e < 16 * 64; e += 256) {
            int r = e >> 6, ii = e & 63;
            sA[r][ii] = Abase[r * HH + c0 + ii];
            sB[r][ii] = Bbase[r * HH + c0 + ii];
        }
        if (tid < 64) sC[tid] = cls[(c0 + tid) * LL + l];
        __syncthreads();

        #pragma unroll 4
        for (int ii = 0; ii < 64; ii += 4) {
            float z0 = sA[ty][ii]     + sB[tx][ii];
            float z1 = sA[ty][ii + 1] + sB[tx][ii + 1];
            float z2 = sA[ty][ii + 2] + sB[tx][ii + 2];
            float z3 = sA[ty][ii + 3] + sB[tx][ii + 3];
            float e0 = erff(z0 * 0.70710678118654752f);   // exact (non-approximate) gelu
            float e1 = erff(z1 * 0.70710678118654752f);
            float e2 = erff(z2 * 0.70710678118654752f);
            float e3 = erff(z3 * 0.70710678118654752f);
            float g0 = 0.5f * z0 * (1.0f + e0);
            float g1 = 0.5f * z1 * (1.0f + e1);
            float g2 = 0.5f * z2 * (1.0f + e2);
            float g3 = 0.5f * z3 * (1.0f + e3);
            acc0 = fmaf(g0, sC[ii],     acc0);
            acc1 = fmaf(g1, sC[ii + 1], acc1);
            acc2 = fmaf(g2, sC[ii + 2], acc2);
            acc3 = fmaf(g3, sC[ii + 3], acc3);
        }
        __syncthreads();
    }

    out[(l * SS + (s0 + ty)) * SS + (t0 + tx)] = (acc0 + acc1) + (acc2 + acc3);
}

// ---------------------------------------------------------------------------
extern "C" void kernel_launch(void* const* d_in, const int* in_sizes, int n_in,
                              void* d_out, int out_size) {
    const float* x    = (const float*)d_in[0];
    const float* Wsrc = (const float*)d_in[1];
    const float* bsrc = (const float*)d_in[2];
    const float* Wtgt = (const float*)d_in[3];
    const float* btgt = (const float*)d_in[4];
    const float* Asrc = (const float*)d_in[5];
    const float* Bsrc = (const float*)d_in[6];
    const float* Atgt = (const float*)d_in[7];
    const float* Btgt = (const float*)d_in[8];
    const float* cls  = (const float*)d_in[9];
    float* out = (float*)d_out;

    gemm_h_kernel  <<<dim3(12, 2, 2), 256>>>(x, Wsrc, bsrc, Wtgt, btgt);
    calc_u_kernel  <<<128, 64>>>(x, Asrc, Atgt);
    expand_ab_kernel<<<dim3(8, LL, 2), 256>>>(Bsrc, Btgt);
    main_kernel    <<<dim3(8, 8, LL), 256>>>(cls, out);
}

// round 5
// speedup vs baseline: 1.5259x; 1.5259x over previous
#include <cuda_runtime.h>
#include <math.h>

#define HH 768
#define SS 128
#define LL 10

// Scratch (no allocation allowed). g_h/g_u/g_ab hold values PRE-SCALED by 1/sqrt(2)
// so the main kernel works directly in x = z/sqrt(2) space.
__device__ float g_h[2][SS * HH];         // h/sqrt2
__device__ float g_u[2][SS * 20];         // (x@A)/sqrt2   (rl = r*10+l)
__device__ float g_ab[2][LL * SS * HH];   // a[l][s][i]/sqrt2, b[l][t][i]/sqrt2

#define INV_SQRT2 0.70710678118654752f
#define SQRT2     1.41421356237309505f

// ---------------------------------------------------------------------------
// Kernel 1: h = (x @ W + bias) * inv_sqrt2   (two 128x768x768 fp32 GEMMs)
// grid (12 i-tiles of 64, 4 s-tiles of 32, 2 mats) = 96 blocks, 256 threads,
// 2x4 outputs per thread.
// ---------------------------------------------------------------------------
__global__ void __launch_bounds__(256) gemm_h_kernel(
        const float* __restrict__ x,
        const float* __restrict__ Wsrc, const float* __restrict__ bsrc,
        const float* __restrict__ Wtgt, const float* __restrict__ btgt) {
    const int mat = blockIdx.z;
    const float* __restrict__ Wm = mat ? Wtgt : Wsrc;
    const float* __restrict__ bm = mat ? btgt : bsrc;
    const int i0 = blockIdx.x * 64;
    const int s0 = blockIdx.y * 32;

    __shared__ __align__(16) float sX[16][32];   // [k][s]
    __shared__ __align__(16) float sW[16][64];   // [k][i]

    const int tid = threadIdx.x;
    const int tx = tid % 16;       // i direction (4 each)
    const int ty = tid / 16;       // s direction (2 each)

    float acc[2][4] = {};

    for (int k0 = 0; k0 < HH; k0 += 16) {
        #pragma unroll
        for (int e = tid; e < 32 * 16; e += 256) {
            int ssi = e >> 4, kk = e & 15;
            sX[kk][ssi] = x[(s0 + ssi) * HH + k0 + kk];
        }
        #pragma unroll
        for (int e = tid; e < 16 * 64; e += 256) {
            int kk = e >> 6, ii = e & 63;
            sW[kk][ii] = Wm[(k0 + kk) * HH + i0 + ii];
        }
        __syncthreads();
        #pragma unroll
        for (int kk = 0; kk < 16; kk++) {
            float2 a2 = *(const float2*)&sX[kk][ty * 2];
            float4 b4 = *(const float4*)&sW[kk][tx * 4];
            float av[2] = {a2.x, a2.y};
            float bv[4] = {b4.x, b4.y, b4.z, b4.w};
            #pragma unroll
            for (int i = 0; i < 2; i++)
                #pragma unroll
                for (int j = 0; j < 4; j++)
                    acc[i][j] = fmaf(av[i], bv[j], acc[i][j]);
        }
        __syncthreads();
    }
    #pragma unroll
    for (int i = 0; i < 2; i++)
        #pragma unroll
        for (int j = 0; j < 4; j++) {
            int s = s0 + ty * 2 + i;
            int ii = i0 + tx * 4 + j;
            g_h[mat][s * HH + ii] = (acc[i][j] + bm[ii]) * INV_SQRT2;
        }
}

// ---------------------------------------------------------------------------
// Kernel 2: u[s][r][l] = (sum_h x[s,h] * A[h,r,l]) * inv_sqrt2
// ---------------------------------------------------------------------------
__global__ void calc_u_kernel(const float* __restrict__ x,
                              const float* __restrict__ Asrc,
                              const float* __restrict__ Atgt) {
    __shared__ float sx[HH];
    const int s = blockIdx.x;
    for (int e = threadIdx.x; e < HH; e += 64) sx[e] = x[s * HH + e];
    __syncthreads();
    const int j = threadIdx.x;
    if (j < 40) {
        const int mat = j / 20;
        const int rl  = j % 20;
        const float* __restrict__ A = mat ? Atgt : Asrc;
        float acc = 0.f;
        #pragma unroll 8
        for (int h = 0; h < HH; h++) acc = fmaf(sx[h], A[h * 20 + rl], acc);
        g_u[mat][s * 20 + rl] = acc * INV_SQRT2;
    }
}

// ---------------------------------------------------------------------------
// Kernel 3: ab[l][s][i] = h'[s][i] + u'[s][0][l]*B[0][i][l] + u'[s][1][l]*B[1][i][l]
// (everything already /sqrt2)
// ---------------------------------------------------------------------------
__global__ void expand_ab_kernel(const float* __restrict__ Bsrc,
                                 const float* __restrict__ Btgt) {
    const int mat = blockIdx.z;
    const int l   = blockIdx.y;
    const int s0  = blockIdx.x * 16;
    const float* __restrict__ Bm = mat ? Btgt : Bsrc;

    __shared__ float sB0[HH];
    __shared__ float sB1[HH];
    __shared__ float su[16][2];

    for (int e = threadIdx.x; e < HH; e += 256) {
        sB0[e] = Bm[(0 * HH + e) * LL + l];
        sB1[e] = Bm[(1 * HH + e) * LL + l];
    }
    if (threadIdx.x < 32) {
        int si = threadIdx.x >> 1, r = threadIdx.x & 1;
        su[si][r] = g_u[mat][(s0 + si) * 20 + r * 10 + l];
    }
    __syncthreads();

    for (int e = threadIdx.x; e < 16 * HH; e += 256) {
        int si = e / HH, ii = e % HH;
        float v = g_h[mat][(s0 + si) * HH + ii]
                + su[si][0] * sB0[ii] + su[si][1] * sB1[ii];
        g_ab[mat][(l * SS + s0 + si) * HH + ii] = v;
    }
}

// ---------------------------------------------------------------------------
// Branch-free gelu term in x = z/sqrt2 space (A&S 7.1.25, |erf err| <= 2.5e-5):
//   q   = 0.5*erfc(|x|) = 0.5*(a1 t + a2 t^2 + a3 t^3) * exp(-x^2),  t=1/(1+p|x|)
//   x*Phi(z) = 0.5x + |x|*(0.5 - q)        (handles both signs, no select)
//   contribution = x*Phi * (sqrt2 * c)
// ---------------------------------------------------------------------------
__device__ __forceinline__ void gelu_acc(float x, float c, float& acc) {
    float ax = fabsf(x);
    float d  = fmaf(0.47047f, ax, 1.0f);
    float t;  asm("rcp.approx.f32 %0, %1;" : "=f"(t) : "f"(d));
    float p  = fmaf(0.3739278f, t, -0.0479399f);   // a3/2, a2/2
    p        = fmaf(p, t, 0.1740121f);             // a1/2
    float pt = p * t;
    float s2 = x * x;
    float u  = s2 * -1.4426950408889634f;          // -x^2 * log2(e)
    float e;  asm("ex2.approx.f32 %0, %1;" : "=f"(e) : "f"(u));
    float q  = pt * e;                             // 0.5*erfc(|x|)
    float r  = 0.5f - q;
    float m  = fmaf(ax, r, 0.5f * x);              // x * Phi(z)
    acc = fmaf(m, c, acc);
}

// ---------------------------------------------------------------------------
// Kernel 4 (main): out[l,s,t] = sum_i gelu(z) * c[i,l], z = sqrt2*(xa+xb)
// grid (16 t-tiles of 8, 8 s-tiles of 16, 10 l) = 1280 blocks, 128 threads.
// ---------------------------------------------------------------------------
__global__ void __launch_bounds__(128, 12) main_kernel(
        const float* __restrict__ cls, float* __restrict__ out) {
    const int l  = blockIdx.z;
    const int s0 = blockIdx.y * 16;
    const int t0 = blockIdx.x * 8;
    const int tid = threadIdx.x;
    const int tx = tid % 8;    // t
    const int ty = tid / 8;    // s (0..15)

    __shared__ __align__(16) float sA[16][68];   // stride 68: float4-aligned, conflict-free
    __shared__ __align__(16) float sB[8][68];
    __shared__ float sC[64];

    const float* __restrict__ Abase = &g_ab[0][(l * SS + s0) * HH];
    const float* __restrict__ Bbase = &g_ab[1][(l * SS + t0) * HH];

    float acc0 = 0.f, acc1 = 0.f, acc2 = 0.f, acc3 = 0.f;

    for (int c0 = 0; c0 < HH; c0 += 64) {
        // stage A: 16 rows x 64 = 256 float4, 2 per thread
        #pragma unroll
        for (int e = tid; e < 256; e += 128) {
            int r = e >> 4, c4 = (e & 15) << 2;
            *(float4*)&sA[r][c4] = *(const float4*)(Abase + r * HH + c0 + c4);
        }
        // stage B: 8 rows x 64 = 128 float4, 1 per thread
        {
            int r = tid >> 4, c4 = (tid & 15) << 2;
            *(float4*)&sB[r][c4] = *(const float4*)(Bbase + r * HH + c0 + c4);
        }
        if (tid < 64) sC[tid] = SQRT2 * cls[(c0 + tid) * LL + l];  // fold sqrt2 into c
        __syncthreads();

        #pragma unroll
        for (int ii = 0; ii < 64; ii += 4) {
            float4 va = *(const float4*)&sA[ty][ii];
            float4 vb = *(const float4*)&sB[tx][ii];
            gelu_acc(va.x + vb.x, sC[ii + 0], acc0);
            gelu_acc(va.y + vb.y, sC[ii + 1], acc1);
            gelu_acc(va.z + vb.z, sC[ii + 2], acc2);
            gelu_acc(va.w + vb.w, sC[ii + 3], acc3);
        }
        __syncthreads();
    }

    out[(l * SS + (s0 + ty)) * SS + (t0 + tx)] = (acc0 + acc1) + (acc2 + acc3);
}

// ---------------------------------------------------------------------------
extern "C" void kernel_launch(void* const* d_in, const int* in_sizes, int n_in,
                              void* d_out, int out_size) {
    const float* x    = (const float*)d_in[0];
    const float* Wsrc = (const float*)d_in[1];
    const float* bsrc = (const float*)d_in[2];
    const float* Wtgt = (const float*)d_in[3];
    const float* btgt = (const float*)d_in[4];
    const float* Asrc = (const float*)d_in[5];
    const float* Bsrc = (const float*)d_in[6];
    const float* Atgt = (const float*)d_in[7];
    const float* Btgt = (const float*)d_in[8];
    const float* cls  = (const float*)d_in[9];
    float* out = (float*)d_out;

    gemm_h_kernel   <<<dim3(12, 4, 2), 256>>>(x, Wsrc, bsrc, Wtgt, btgt);
    calc_u_kernel   <<<128, 64>>>(x, Asrc, Atgt);
    expand_ab_kernel<<<dim3(8, LL, 2), 256>>>(Bsrc, Btgt);
    main_kernel     <<<dim3(16, 8, LL), 128>>>(cls, out);
}

// round 6
// speedup vs baseline: 2.2233x; 1.4570x over previous
#include <cuda_runtime.h>
#include <math.h>

#define HH 768
#define SS 128
#define LL 10

typedef unsigned long long ull;

// Scratch (no allocation allowed). Raw (unscaled) halves; main works in z-space.
__device__ float g_h[2][SS * HH];         // x@W + bias
__device__ float g_u[2][SS * 20];         // x@A   (rl = r*10+l)
__device__ float g_ab[2][LL * SS * HH];   // a[l][s][i], b[l][t][i]

// Packed f32x2 ops (sm_100+). ptxas will not auto-emit these.
#define ADD2(o,a,b)   asm("add.rn.f32x2 %0,%1,%2;"    : "=l"(o) : "l"(a), "l"(b))
#define MUL2(o,a,b)   asm("mul.rn.f32x2 %0,%1,%2;"    : "=l"(o) : "l"(a), "l"(b))
#define FMA2(o,a,b,c) asm("fma.rn.f32x2 %0,%1,%2,%3;" : "=l"(o) : "l"(a), "l"(b), "l"(c))

// ---------------------------------------------------------------------------
// Kernel 1: h = x @ W + bias   (two 128x768x768 fp32 GEMMs)
// ---------------------------------------------------------------------------
__global__ void __launch_bounds__(256) gemm_h_kernel(
        const float* __restrict__ x,
        const float* __restrict__ Wsrc, const float* __restrict__ bsrc,
        const float* __restrict__ Wtgt, const float* __restrict__ btgt) {
    const int mat = blockIdx.z;
    const float* __restrict__ Wm = mat ? Wtgt : Wsrc;
    const float* __restrict__ bm = mat ? btgt : bsrc;
    const int i0 = blockIdx.x * 64;
    const int s0 = blockIdx.y * 32;

    __shared__ __align__(16) float sX[16][32];   // [k][s]
    __shared__ __align__(16) float sW[16][64];   // [k][i]

    const int tid = threadIdx.x;
    const int tx = tid % 16;       // i direction (4 each)
    const int ty = tid / 16;       // s direction (2 each)

    float acc[2][4] = {};

    for (int k0 = 0; k0 < HH; k0 += 16) {
        #pragma unroll
        for (int e = tid; e < 32 * 16; e += 256) {
            int ssi = e >> 4, kk = e & 15;
            sX[kk][ssi] = x[(s0 + ssi) * HH + k0 + kk];
        }
        #pragma unroll
        for (int e = tid; e < 16 * 64; e += 256) {
            int kk = e >> 6, ii = e & 63;
            sW[kk][ii] = Wm[(k0 + kk) * HH + i0 + ii];
        }
        __syncthreads();
        #pragma unroll
        for (int kk = 0; kk < 16; kk++) {
            float2 a2 = *(const float2*)&sX[kk][ty * 2];
            float4 b4 = *(const float4*)&sW[kk][tx * 4];
            float av[2] = {a2.x, a2.y};
            float bv[4] = {b4.x, b4.y, b4.z, b4.w};
            #pragma unroll
            for (int i = 0; i < 2; i++)
                #pragma unroll
                for (int j = 0; j < 4; j++)
                    acc[i][j] = fmaf(av[i], bv[j], acc[i][j]);
        }
        __syncthreads();
    }
    #pragma unroll
    for (int i = 0; i < 2; i++)
        #pragma unroll
        for (int j = 0; j < 4; j++) {
            int s = s0 + ty * 2 + i;
            int ii = i0 + tx * 4 + j;
            g_h[mat][s * HH + ii] = acc[i][j] + bm[ii];
        }
}

// ---------------------------------------------------------------------------
// Kernel 2: u[s][r][l] = sum_h x[s,h] * A[h,r,l]
// ---------------------------------------------------------------------------
__global__ void calc_u_kernel(const float* __restrict__ x,
                              const float* __restrict__ Asrc,
                              const float* __restrict__ Atgt) {
    __shared__ float sx[HH];
    const int s = blockIdx.x;
    for (int e = threadIdx.x; e < HH; e += 64) sx[e] = x[s * HH + e];
    __syncthreads();
    const int j = threadIdx.x;
    if (j < 40) {
        const int mat = j / 20;
        const int rl  = j % 20;
        const float* __restrict__ A = mat ? Atgt : Asrc;
        float acc = 0.f;
        #pragma unroll 8
        for (int h = 0; h < HH; h++) acc = fmaf(sx[h], A[h * 20 + rl], acc);
        g_u[mat][s * 20 + rl] = acc;
    }
}

// ---------------------------------------------------------------------------
// Kernel 3: ab[l][s][i] = h[s][i] + u[s][0][l]*B[0][i][l] + u[s][1][l]*B[1][i][l]
// ---------------------------------------------------------------------------
__global__ void expand_ab_kernel(const float* __restrict__ Bsrc,
                                 const float* __restrict__ Btgt) {
    const int mat = blockIdx.z;
    const int l   = blockIdx.y;
    const int s0  = blockIdx.x * 16;
    const float* __restrict__ Bm = mat ? Btgt : Bsrc;

    __shared__ float sB0[HH];
    __shared__ float sB1[HH];
    __shared__ float su[16][2];

    for (int e = threadIdx.x; e < HH; e += 256) {
        sB0[e] = Bm[(0 * HH + e) * LL + l];
        sB1[e] = Bm[(1 * HH + e) * LL + l];
    }
    if (threadIdx.x < 32) {
        int si = threadIdx.x >> 1, r = threadIdx.x & 1;
        su[si][r] = g_u[mat][(s0 + si) * 20 + r * 10 + l];
    }
    __syncthreads();

    for (int e = threadIdx.x; e < 16 * HH; e += 256) {
        int si = e / HH, ii = e % HH;
        float v = g_h[mat][(s0 + si) * HH + ii]
                + su[si][0] * sB0[ii] + su[si][1] * sB1[ii];
        g_ab[mat][(l * SS + s0 + si) * HH + ii] = v;
    }
}

// ---------------------------------------------------------------------------
// gelu pair: processes 2 elements packed in f32x2.
//   z = a+b;  arg = z*(C0 + C1*z^2);  th = tanh(arg)  [1 MUFU per elt]
//   contribution = (0.5c)*z*(1+th)  ->  acc_t += w*th, acc_w += w,  w=(0.5c)*z
// ---------------------------------------------------------------------------
__device__ __forceinline__ void gelu2(ull a2, ull b2, ull c2, ull C0, ull C1,
                                      ull& acc_t, ull& acc_w) {
    ull z2; ADD2(z2, a2, b2);
    ull t2; MUL2(t2, z2, z2);
    ull p2; FMA2(p2, C1, t2, C0);
    ull g2; MUL2(g2, z2, p2);
    float glo, ghi;
    asm("mov.b64 {%0,%1}, %2;" : "=f"(glo), "=f"(ghi) : "l"(g2));
    float tlo, thi;
    asm("tanh.approx.f32 %0, %1;" : "=f"(tlo) : "f"(glo));
    asm("tanh.approx.f32 %0, %1;" : "=f"(thi) : "f"(ghi));
    ull th2;
    asm("mov.b64 %0, {%1,%2};" : "=l"(th2) : "f"(tlo), "f"(thi));
    ull w2; MUL2(w2, c2, z2);
    FMA2(acc_t, w2, th2, acc_t);
    ADD2(acc_w, acc_w, w2);
}

// ---------------------------------------------------------------------------
// Kernel 4 (main): out[l,s,t] = sum_i gelu(a+b) * c
// grid (16 t-tiles of 8, 8 s-tiles of 16, 10 l) = 1280 blocks, 128 threads.
// ---------------------------------------------------------------------------
__global__ void __launch_bounds__(128, 12) main_kernel(
        const float* __restrict__ cls, float* __restrict__ out) {
    const int l  = blockIdx.z;
    const int s0 = blockIdx.y * 16;
    const int t0 = blockIdx.x * 8;
    const int tid = threadIdx.x;
    const int tx = tid % 8;    // t
    const int ty = tid / 8;    // s (0..15)

    __shared__ __align__(16) float sA[16][68];   // 272B rows: 8B-aligned pair loads
    __shared__ __align__(16) float sB[8][68];
    __shared__ __align__(16) float sC[64];

    const float* __restrict__ Abase = &g_ab[0][(l * SS + s0) * HH];
    const float* __restrict__ Bbase = &g_ab[1][(l * SS + t0) * HH];

    ull C0_2, C1_2;
    asm("mov.b64 %0, {%1,%1};" : "=l"(C0_2) : "f"(0.7978845608028654f));
    asm("mov.b64 %0, {%1,%1};" : "=l"(C1_2) : "f"(0.035677408136300125f));

    ull acctA = 0ull, accwA = 0ull, acctB = 0ull, accwB = 0ull;

    for (int c0 = 0; c0 < HH; c0 += 64) {
        // stage A: 16 rows x 64 = 256 float4, 2 per thread
        #pragma unroll
        for (int e = tid; e < 256; e += 128) {
            int r = e >> 4, c4 = (e & 15) << 2;
            *(float4*)&sA[r][c4] = *(const float4*)(Abase + r * HH + c0 + c4);
        }
        // stage B: 8 rows x 64 = 128 float4, 1 per thread
        {
            int r = tid >> 4, c4 = (tid & 15) << 2;
            *(float4*)&sB[r][c4] = *(const float4*)(Bbase + r * HH + c0 + c4);
        }
        if (tid < 64) sC[tid] = 0.5f * cls[(c0 + tid) * LL + l];  // fold 0.5 into c
        __syncthreads();

        #pragma unroll
        for (int ii = 0; ii < 64; ii += 4) {
            ull a01 = *(const ull*)&sA[ty][ii];
            ull a23 = *(const ull*)&sA[ty][ii + 2];
            ull b01 = *(const ull*)&sB[tx][ii];
            ull b23 = *(const ull*)&sB[tx][ii + 2];
            ull c01 = *(const ull*)&sC[ii];
            ull c23 = *(const ull*)&sC[ii + 2];
            gelu2(a01, b01, c01, C0_2, C1_2, acctA, accwA);
            gelu2(a23, b23, c23, C0_2, C1_2, acctB, accwB);
        }
        __syncthreads();
    }

    float t0f, t1f, t2f, t3f, w0f, w1f, w2f, w3f;
    asm("mov.b64 {%0,%1}, %2;" : "=f"(t0f), "=f"(t1f) : "l"(acctA));
    asm("mov.b64 {%0,%1}, %2;" : "=f"(t2f), "=f"(t3f) : "l"(acctB));
    asm("mov.b64 {%0,%1}, %2;" : "=f"(w0f), "=f"(w1f) : "l"(accwA));
    asm("mov.b64 {%0,%1}, %2;" : "=f"(w2f), "=f"(w3f) : "l"(accwB));
    float res = ((t0f + t1f) + (t2f + t3f)) + ((w0f + w1f) + (w2f + w3f));

    out[(l * SS + (s0 + ty)) * SS + (t0 + tx)] = res;
}

// ---------------------------------------------------------------------------
extern "C" void kernel_launch(void* const* d_in, const int* in_sizes, int n_in,
                              void* d_out, int out_size) {
    const float* x    = (const float*)d_in[0];
    const float* Wsrc = (const float*)d_in[1];
    const float* bsrc = (const float*)d_in[2];
    const float* Wtgt = (const float*)d_in[3];
    const float* btgt = (const float*)d_in[4];
    const float* Asrc = (const float*)d_in[5];
    const float* Bsrc = (const float*)d_in[6];
    const float* Atgt = (const float*)d_in[7];
    const float* Btgt = (const float*)d_in[8];
    const float* cls  = (const float*)d_in[9];
    float* out = (float*)d_out;

    gemm_h_kernel   <<<dim3(12, 4, 2), 256>>>(x, Wsrc, bsrc, Wtgt, btgt);
    calc_u_kernel   <<<128, 64>>>(x, Asrc, Atgt);
    expand_ab_kernel<<<dim3(8, LL, 2), 256>>>(Bsrc, Btgt);
    main_kernel     <<<dim3(16, 8, LL), 128>>>(cls, out);
}

// round 7
// speedup vs baseline: 2.5149x; 1.1312x over previous
#include <cuda_runtime.h>
#include <math.h>

#define HH 768
#define SS 128
#define LL 10

typedef unsigned long long ull;

// Scratch (no allocation allowed)
__device__ float g_h[2][SS * HH];          // x@W + bias
__device__ float g_u[2][SS * 20];          // x@A   (rl = r*10+l)
__device__ float g_Bt[2 * LL * 2 * HH];    // Bt[mat][l][r][i] = B[mat][(r*H+i)*L + l]
__device__ float g_ct[LL * HH];            // ct[l][i] = 0.5 * classifier[i*L + l]

// Packed f32x2 ops (sm_100+). ptxas will not auto-emit these.
#define ADD2(o,a,b)   asm("add.rn.f32x2 %0,%1,%2;"    : "=l"(o) : "l"(a), "l"(b))
#define MUL2(o,a,b)   asm("mul.rn.f32x2 %0,%1,%2;"    : "=l"(o) : "l"(a), "l"(b))
#define FMA2(o,a,b,c) asm("fma.rn.f32x2 %0,%1,%2,%3;" : "=l"(o) : "l"(a), "l"(b), "l"(c))

// ---------------------------------------------------------------------------
// Prep kernel: one launch does gemm_h (blocks 0..95), u (96..223),
// transposes (224..231). 256 threads.
// ---------------------------------------------------------------------------
__global__ void __launch_bounds__(256) prep_kernel(
        const float* __restrict__ x,
        const float* __restrict__ Wsrc, const float* __restrict__ bsrc,
        const float* __restrict__ Wtgt, const float* __restrict__ btgt,
        const float* __restrict__ Asrc, const float* __restrict__ Bsrc,
        const float* __restrict__ Atgt, const float* __restrict__ Btgt,
        const float* __restrict__ cls) {
    const int bid = blockIdx.x;
    const int tid = threadIdx.x;

    if (bid < 96) {
        // ---- gemm: h = x @ W + bias. tile 32s x 64i, 2x4 per thread ----
        const int it  = bid % 12;
        const int st  = (bid / 12) % 4;
        const int mat = bid / 48;
        const float* __restrict__ Wm = mat ? Wtgt : Wsrc;
        const float* __restrict__ bm = mat ? btgt : bsrc;
        const int i0 = it * 64;
        const int s0 = st * 32;

        __shared__ __align__(16) float sX[16][32];
        __shared__ __align__(16) float sW[16][64];

        const int tx = tid % 16;
        const int ty = tid / 16;
        float acc[2][4] = {};

        for (int k0 = 0; k0 < HH; k0 += 16) {
            #pragma unroll
            for (int e = tid; e < 32 * 16; e += 256) {
                int ssi = e >> 4, kk = e & 15;
                sX[kk][ssi] = x[(s0 + ssi) * HH + k0 + kk];
            }
            #pragma unroll
            for (int e = tid; e < 16 * 64; e += 256) {
                int kk = e >> 6, ii = e & 63;
                sW[kk][ii] = Wm[(k0 + kk) * HH + i0 + ii];
            }
            __syncthreads();
            #pragma unroll
            for (int kk = 0; kk < 16; kk++) {
                float2 a2 = *(const float2*)&sX[kk][ty * 2];
                float4 b4 = *(const float4*)&sW[kk][tx * 4];
                float av[2] = {a2.x, a2.y};
                float bv[4] = {b4.x, b4.y, b4.z, b4.w};
                #pragma unroll
                for (int i = 0; i < 2; i++)
                    #pragma unroll
                    for (int j = 0; j < 4; j++)
                        acc[i][j] = fmaf(av[i], bv[j], acc[i][j]);
            }
            __syncthreads();
        }
        #pragma unroll
        for (int i = 0; i < 2; i++)
            #pragma unroll
            for (int j = 0; j < 4; j++) {
                int s  = s0 + ty * 2 + i;
                int ii = i0 + tx * 4 + j;
                g_h[mat][s * HH + ii] = acc[i][j] + bm[ii];
            }
    } else if (bid < 224) {
        // ---- u[s][r][l] = sum_h x[s,h]*A[h,r,l], 4-way k-split ----
        __shared__ float sx[HH];
        __shared__ float spart[4][40];
        const int s = bid - 96;
        for (int e = tid; e < HH; e += 256) sx[e] = x[s * HH + e];
        __syncthreads();
        const int seg = tid >> 6;     // 0..3
        const int j   = tid & 63;
        if (j < 40) {
            const int mat = j / 20, rl = j % 20;
            const float* __restrict__ A = mat ? Atgt : Asrc;
            float acc = 0.f;
            const int h0 = seg * 192;
            #pragma unroll 8
            for (int h = h0; h < h0 + 192; h++)
                acc = fmaf(sx[h], A[h * 20 + rl], acc);
            spart[seg][j] = acc;
        }
        __syncthreads();
        if (tid < 40) {
            float v = spart[0][tid] + spart[1][tid] + spart[2][tid] + spart[3][tid];
            g_u[tid / 20][s * 20 + tid % 20] = v;
        }
    } else {
        // ---- transposes: Bt and ct ----
        const int idx0 = (bid - 224) * 256 + tid;
        for (int n = idx0; n < 2 * LL * 2 * HH; n += 8 * 256) {
            int i   = n % HH;
            int rem = n / HH;            // 0..39
            int r   = rem % 2;
            int l   = (rem / 2) % LL;
            int mat = rem / (2 * LL);
            const float* __restrict__ Bm = mat ? Btgt : Bsrc;
            g_Bt[((mat * LL + l) * 2 + r) * HH + i] = Bm[(r * HH + i) * LL + l];
        }
        for (int n = idx0; n < LL * HH; n += 8 * 256) {
            int i = n % HH, l = n / HH;
            g_ct[l * HH + i] = 0.5f * cls[i * LL + l];
        }
    }
}

// ---------------------------------------------------------------------------
// gelu pair: 2 elements packed f32x2.
//   z = a+b;  arg = z*(C0 + C1*z^2);  th = tanh(arg)
//   gelu(z)*c = w*th + w,  w = (0.5c)*z   (0.5 prefolded into c)
// ---------------------------------------------------------------------------
__device__ __forceinline__ void gelu2(ull a2, ull b2, ull c2, ull C0, ull C1,
                                      ull& acc_t, ull& acc_w) {
    ull z2; ADD2(z2, a2, b2);
    ull t2; MUL2(t2, z2, z2);
    ull p2; FMA2(p2, C1, t2, C0);
    ull g2; MUL2(g2, z2, p2);
    float glo, ghi;
    asm("mov.b64 {%0,%1}, %2;" : "=f"(glo), "=f"(ghi) : "l"(g2));
    float tlo, thi;
    asm("tanh.approx.f32 %0, %1;" : "=f"(tlo) : "f"(glo));
    asm("tanh.approx.f32 %0, %1;" : "=f"(thi) : "f"(ghi));
    ull th2;
    asm("mov.b64 %0, {%1,%2};" : "=l"(th2) : "f"(tlo), "f"(thi));
    ull w2; MUL2(w2, c2, z2);
    FMA2(acc_t, w2, th2, acc_t);
    ADD2(acc_w, acc_w, w2);
}

// ---------------------------------------------------------------------------
// Main: out[l,s,t] = sum_i gelu(a+b)*c.  Fused expand: a/b staged on the fly
// from g_h + u*Bt.  Tile 16s x 16t, 64 threads, 2x2 per thread, grid 640.
// Row stride 70 floats: 8B-aligned pairs, conflict-free strided row access.
// ---------------------------------------------------------------------------
#define STRD 70

__global__ void __launch_bounds__(64, 8) main_kernel(float* __restrict__ out) {
    const int l  = blockIdx.z;
    const int s0 = blockIdx.y * 16;
    const int t0 = blockIdx.x * 16;
    const int tid = threadIdx.x;
    const int txx = tid & 7;    // t position (rows txx, txx+8)
    const int tyy = tid >> 3;   // s position (rows tyy, tyy+8)

    __shared__ __align__(16) float sA[16][STRD];
    __shared__ __align__(16) float sB[16][STRD];
    __shared__ __align__(16) float sBt[2][2][HH];
    __shared__ __align__(16) float sC[HH];
    __shared__ float su_a[16][2], su_b[16][2];

    // ---- preload Bt(l), ct(l), u values ----
    for (int e = tid; e < 768; e += 64) {   // 768 float4 = 3072 floats
        int mr = e / 192;                   // 0..3 -> (mat, r)
        int i4 = (e % 192) * 4;
        int mat = mr >> 1, r = mr & 1;
        *(float4*)&sBt[mat][r][i4] =
            *(const float4*)&g_Bt[((mat * LL + l) * 2 + r) * HH + i4];
    }
    for (int e = tid; e < 192; e += 64)
        *(float4*)&sC[e * 4] = *(const float4*)&g_ct[l * HH + e * 4];
    if (tid < 32) {
        int si = tid >> 1, r = tid & 1;
        su_a[si][r] = g_u[0][(s0 + si) * 20 + r * 10 + l];
        su_b[si][r] = g_u[1][(t0 + si) * 20 + r * 10 + l];
    }

    ull C0_2, C1_2;
    asm("mov.b64 %0, {%1,%1};" : "=l"(C0_2) : "f"(0.7978845608028654f));
    asm("mov.b64 %0, {%1,%1};" : "=l"(C1_2) : "f"(0.035677408136300125f));

    ull t00 = 0, w00 = 0, t01 = 0, w01 = 0, t10 = 0, w10 = 0, t11 = 0, w11 = 0;

    for (int c0 = 0; c0 < HH; c0 += 64) {
        __syncthreads();   // also covers preload on first iteration
        // ---- stage tiles (fused expand): v = h + u0*Bt0 + u1*Bt1, float2 units
        #pragma unroll
        for (int e = tid; e < 512; e += 64) {     // 16 rows x 32 f2
            int r  = e >> 5;
            int c2 = (e & 31) << 1;
            float2 h2 = *(const float2*)&g_h[0][(s0 + r) * HH + c0 + c2];
            float2 q0 = *(const float2*)&sBt[0][0][c0 + c2];
            float2 q1 = *(const float2*)&sBt[0][1][c0 + c2];
            float u0 = su_a[r][0], u1 = su_a[r][1];
            float2 v;
            v.x = fmaf(u1, q1.x, fmaf(u0, q0.x, h2.x));
            v.y = fmaf(u1, q1.y, fmaf(u0, q0.y, h2.y));
            *(float2*)&sA[r][c2] = v;
        }
        #pragma unroll
        for (int e = tid; e < 512; e += 64) {
            int r  = e >> 5;
            int c2 = (e & 31) << 1;
            float2 h2 = *(const float2*)&g_h[1][(t0 + r) * HH + c0 + c2];
            float2 q0 = *(const float2*)&sBt[1][0][c0 + c2];
            float2 q1 = *(const float2*)&sBt[1][1][c0 + c2];
            float u0 = su_b[r][0], u1 = su_b[r][1];
            float2 v;
            v.x = fmaf(u1, q1.x, fmaf(u0, q0.x, h2.x));
            v.y = fmaf(u1, q1.y, fmaf(u0, q0.y, h2.y));
            *(float2*)&sB[r][c2] = v;
        }
        __syncthreads();

        // ---- inner: 32 i-pairs, 4 outputs per thread ----
        #pragma unroll 4
        for (int ii = 0; ii < 64; ii += 2) {
            ull a0 = *(const ull*)&sA[tyy][ii];
            ull a1 = *(const ull*)&sA[tyy + 8][ii];
            ull b0 = *(const ull*)&sB[txx][ii];
            ull b1 = *(const ull*)&sB[txx + 8][ii];
            ull cc = *(const ull*)&sC[c0 + ii];
            gelu2(a0, b0, cc, C0_2, C1_2, t00, w00);
            gelu2(a0, b1, cc, C0_2, C1_2, t01, w01);
            gelu2(a1, b0, cc, C0_2, C1_2, t10, w10);
            gelu2(a1, b1, cc, C0_2, C1_2, t11, w11);
        }
    }

    // ---- epilogue ----
    float r00, r01, r10, r11;
    {
        float xlo, xhi, ylo, yhi;
        asm("mov.b64 {%0,%1}, %2;" : "=f"(xlo), "=f"(xhi) : "l"(t00));
        asm("mov.b64 {%0,%1}, %2;" : "=f"(ylo), "=f"(yhi) : "l"(w00));
        r00 = (xlo + xhi) + (ylo + yhi);
        asm("mov.b64 {%0,%1}, %2;" : "=f"(xlo), "=f"(xhi) : "l"(t01));
        asm("mov.b64 {%0,%1}, %2;" : "=f"(ylo), "=f"(yhi) : "l"(w01));
        r01 = (xlo + xhi) + (ylo + yhi);
        asm("mov.b64 {%0,%1}, %2;" : "=f"(xlo), "=f"(xhi) : "l"(t10));
        asm("mov.b64 {%0,%1}, %2;" : "=f"(ylo), "=f"(yhi) : "l"(w10));
        r10 = (xlo + xhi) + (ylo + yhi);
        asm("mov.b64 {%0,%1}, %2;" : "=f"(xlo), "=f"(xhi) : "l"(t11));
        asm("mov.b64 {%0,%1}, %2;" : "=f"(ylo), "=f"(yhi) : "l"(w11));
        r11 = (xlo + xhi) + (ylo + yhi);
    }

    const int sa = s0 + tyy, sb = s0 + tyy + 8;
    const int ta = t0 + txx, tb = t0 + txx + 8;
    out[(l * SS + sa) * SS + ta] = r00;
    out[(l * SS + sa) * SS + tb] = r01;
    out[(l * SS + sb) * SS + ta] = r10;
    out[(l * SS + sb) * SS + tb] = r11;
}

// ---------------------------------------------------------------------------
extern "C" void kernel_launch(void* const* d_in, const int* in_sizes, int n_in,
                              void* d_out, int out_size) {
    const float* x    = (const float*)d_in[0];
    const float* Wsrc = (const float*)d_in[1];
    const float* bsrc = (const float*)d_in[2];
    const float* Wtgt = (const float*)d_in[3];
    const float* btgt = (const float*)d_in[4];
    const float* Asrc = (const float*)d_in[5];
    const float* Bsrc = (const float*)d_in[6];
    const float* Atgt = (const float*)d_in[7];
    const float* Btgt = (const float*)d_in[8];
    const float* cls  = (const float*)d_in[9];
    float* out = (float*)d_out;

    prep_kernel<<<232, 256>>>(x, Wsrc, bsrc, Wtgt, btgt,
                              Asrc, Bsrc, Atgt, Btgt, cls);
    main_kernel<<<dim3(8, 8, LL), 64>>>(out);
}

// round 8
// speedup vs baseline: 2.7642x; 1.0991x over previous
#include <cuda_runtime.h>
#include <math.h>

#define HH 768
#define SS 128
#define LL 10

typedef unsigned long long ull;

// Scratch (no allocation allowed)
__device__ float g_h[2][SS * HH];          // x@W + bias
__device__ float g_u[2][SS * 20];          // x@A   (rl = r*10+l)
__device__ float g_Bt[2 * LL * 2 * HH];    // Bt[mat][l][r][i] = B[mat][(r*H+i)*L + l]
__device__ float g_ct[LL * HH];            // ct[l][i] = 0.5 * classifier[i*L + l]
__device__ float g_ab[2][LL * SS * HH];    // a[l][s][i], b[l][t][i]
__device__ float g_cab[2][LL * SS];        // Ca[l][s] = sum_i ct*a ; Cb[l][t]

// Packed f32x2 ops (sm_100+). ptxas will not auto-emit these.
#define ADD2(o,a,b)   asm("add.rn.f32x2 %0,%1,%2;"    : "=l"(o) : "l"(a), "l"(b))
#define MUL2(o,a,b)   asm("mul.rn.f32x2 %0,%1,%2;"    : "=l"(o) : "l"(a), "l"(b))
#define FMA2(o,a,b,c) asm("fma.rn.f32x2 %0,%1,%2,%3;" : "=l"(o) : "l"(a), "l"(b), "l"(c))

// ---------------------------------------------------------------------------
// Prep kernel: gemm_h (blocks 0..95), u (96..223), transposes (224..231).
// ---------------------------------------------------------------------------
__global__ void __launch_bounds__(256) prep_kernel(
        const float* __restrict__ x,
        const float* __restrict__ Wsrc, const float* __restrict__ bsrc,
        const float* __restrict__ Wtgt, const float* __restrict__ btgt,
        const float* __restrict__ Asrc, const float* __restrict__ Bsrc,
        const float* __restrict__ Atgt, const float* __restrict__ Btgt,
        const float* __restrict__ cls) {
    const int bid = blockIdx.x;
    const int tid = threadIdx.x;

    if (bid < 96) {
        // ---- gemm: h = x @ W + bias. tile 32s x 64i, 2s x 4i per thread,
        //      f32x2 accumulation + register double-buffered staging ----
        const int it  = bid % 12;
        const int st  = (bid / 12) % 4;
        const int mat = bid / 48;
        const float* __restrict__ Wm = mat ? Wtgt : Wsrc;
        const float* __restrict__ bm = mat ? btgt : bsrc;
        const int i0 = it * 64;
        const int s0 = st * 32;

        __shared__ float sX[16][32];                  // [k][s]
        __shared__ __align__(16) float sW[16][64];    // [k][i]

        const int tx = tid & 15;
        const int ty = tid >> 4;
        ull acc00 = 0, acc01 = 0, acc10 = 0, acc11 = 0;

        // prefetch chunk 0
        float px0, px1; float4 pw;
        {
            int e0 = tid, e1 = tid + 256;
            px0 = x[(s0 + (e0 >> 4)) * HH + (e0 & 15)];
            px1 = x[(s0 + (e1 >> 4)) * HH + (e1 & 15)];
            int kk = tid >> 4, i4 = (tid & 15) << 2;
            pw = *(const float4*)&Wm[kk * HH + i0 + i4];
        }

        for (int k0 = 0; k0 < HH; k0 += 16) {
            __syncthreads();
            {   // commit prefetched chunk to smem
                int e0 = tid, e1 = tid + 256;
                sX[e0 & 15][e0 >> 4] = px0;
                sX[e1 & 15][e1 >> 4] = px1;
                int kk = tid >> 4, i4 = (tid & 15) << 2;
                *(float4*)&sW[kk][i4] = pw;
            }
            __syncthreads();
            if (k0 + 16 < HH) {   // issue next chunk's loads (latency hidden)
                int e0 = tid, e1 = tid + 256;
                px0 = x[(s0 + (e0 >> 4)) * HH + k0 + 16 + (e0 & 15)];
                px1 = x[(s0 + (e1 >> 4)) * HH + k0 + 16 + (e1 & 15)];
                int kk = tid >> 4, i4 = (tid & 15) << 2;
                pw = *(const float4*)&Wm[(k0 + 16 + kk) * HH + i0 + i4];
            }
            #pragma unroll
            for (int kk = 0; kk < 16; kk++) {
                float2 a2 = *(const float2*)&sX[kk][ty * 2];
                ull b01 = *(const ull*)&sW[kk][tx * 4];
                ull b23 = *(const ull*)&sW[kk][tx * 4 + 2];
                ull a0d, a1d;
                asm("mov.b64 %0,{%1,%1};" : "=l"(a0d) : "f"(a2.x));
                asm("mov.b64 %0,{%1,%1};" : "=l"(a1d) : "f"(a2.y));
                FMA2(acc00, a0d, b01, acc00);
                FMA2(acc01, a0d, b23, acc01);
                FMA2(acc10, a1d, b01, acc10);
                FMA2(acc11, a1d, b23, acc11);
            }
        }
        // epilogue
        float v[2][4];
        asm("mov.b64 {%0,%1}, %2;" : "=f"(v[0][0]), "=f"(v[0][1]) : "l"(acc00));
        asm("mov.b64 {%0,%1}, %2;" : "=f"(v[0][2]), "=f"(v[0][3]) : "l"(acc01));
        asm("mov.b64 {%0,%1}, %2;" : "=f"(v[1][0]), "=f"(v[1][1]) : "l"(acc10));
        asm("mov.b64 {%0,%1}, %2;" : "=f"(v[1][2]), "=f"(v[1][3]) : "l"(acc11));
        #pragma unroll
        for (int i = 0; i < 2; i++)
            #pragma unroll
            for (int j = 0; j < 4; j++) {
                int s  = s0 + ty * 2 + i;
                int ii = i0 + tx * 4 + j;
                g_h[mat][s * HH + ii] = v[i][j] + bm[ii];
            }
    } else if (bid < 224) {
        // ---- u[s][r][l] = sum_h x[s,h]*A[h,r,l], 4-way k-split ----
        __shared__ float sx[HH];
        __shared__ float spart[4][40];
        const int s = bid - 96;
        for (int e = tid; e < HH; e += 256) sx[e] = x[s * HH + e];
        __syncthreads();
        const int seg = tid >> 6;
        const int j   = tid & 63;
        if (j < 40) {
            const int mat = j / 20, rl = j % 20;
            const float* __restrict__ A = mat ? Atgt : Asrc;
            float acc = 0.f;
            const int h0 = seg * 192;
            #pragma unroll 8
            for (int h = h0; h < h0 + 192; h++)
                acc = fmaf(sx[h], A[h * 20 + rl], acc);
            spart[seg][j] = acc;
        }
        __syncthreads();
        if (tid < 40) {
            float vv = spart[0][tid] + spart[1][tid] + spart[2][tid] + spart[3][tid];
            g_u[tid / 20][s * 20 + tid % 20] = vv;
        }
    } else {
        // ---- transposes: Bt and ct ----
        const int idx0 = (bid - 224) * 256 + tid;
        for (int n = idx0; n < 2 * LL * 2 * HH; n += 8 * 256) {
            int i   = n % HH;
            int rem = n / HH;
            int r   = rem % 2;
            int l   = (rem / 2) % LL;
            int mat = rem / (2 * LL);
            const float* __restrict__ Bm = mat ? Btgt : Bsrc;
            g_Bt[((mat * LL + l) * 2 + r) * HH + i] = Bm[(r * HH + i) * LL + l];
        }
        for (int n = idx0; n < LL * HH; n += 8 * 256) {
            int i = n % HH, l = n / HH;
            g_ct[l * HH + i] = 0.5f * cls[i * LL + l];
        }
    }
}

// ---------------------------------------------------------------------------
// Expand kernel: ab = h + u0*Bt0 + u1*Bt1 ; Ca/Cb = sum_i ct*ab  (rank-1 part)
// grid (8 s-chunks, LL, 2 mats) = 160 blocks, 256 threads.
// Thread layout: row = tid>>4 (16 rows), lane16 = tid&15 covers i in float4s.
// ---------------------------------------------------------------------------
__global__ void __launch_bounds__(256) expand_kernel() {
    const int mat = blockIdx.z;
    const int l   = blockIdx.y;
    const int s0  = blockIdx.x * 16;
    const int tid = threadIdx.x;

    __shared__ __align__(16) float sBt0[HH], sBt1[HH], sCt[HH];
    __shared__ float su[16][2];

    for (int e = tid; e < HH; e += 256) {
        sBt0[e] = g_Bt[((mat * LL + l) * 2 + 0) * HH + e];
        sBt1[e] = g_Bt[((mat * LL + l) * 2 + 1) * HH + e];
        sCt[e]  = g_ct[l * HH + e];
    }
    if (tid < 32) {
        int si = tid >> 1, r = tid & 1;
        su[si][r] = g_u[mat][(s0 + si) * 20 + r * 10 + l];
    }
    __syncthreads();

    const int row    = tid >> 4;
    const int lane16 = tid & 15;
    const float u0 = su[row][0], u1 = su[row][1];
    const float* __restrict__ hrow = &g_h[mat][(s0 + row) * HH];
    float* __restrict__ orow = &g_ab[mat][(l * SS + s0 + row) * HH];

    float ca = 0.f;
    #pragma unroll
    for (int j = 0; j < 12; j++) {
        int i4 = lane16 * 4 + j * 64;
        float4 h4 = *(const float4*)&hrow[i4];
        float4 q0 = *(const float4*)&sBt0[i4];
        float4 q1 = *(const float4*)&sBt1[i4];
        float4 c4 = *(const float4*)&sCt[i4];
        float4 v;
        v.x = fmaf(u1, q1.x, fmaf(u0, q0.x, h4.x));
        v.y = fmaf(u1, q1.y, fmaf(u0, q0.y, h4.y));
        v.z = fmaf(u1, q1.z, fmaf(u0, q0.z, h4.z));
        v.w = fmaf(u1, q1.w, fmaf(u0, q0.w, h4.w));
        *(float4*)&orow[i4] = v;
        ca = fmaf(c4.x, v.x, ca); ca = fmaf(c4.y, v.y, ca);
        ca = fmaf(c4.z, v.z, ca); ca = fmaf(c4.w, v.w, ca);
    }
    #pragma unroll
    for (int o = 8; o; o >>= 1) ca += __shfl_xor_sync(0xffffffffu, ca, o, 16);
    if (lane16 == 0) g_cab[mat][l * SS + s0 + row] = ca;
}

// ---------------------------------------------------------------------------
// gelu pair (tanh-only accumulator; the Sum(w) part is rank-1 -> Ca+Cb):
//   z = a+b;  arg = z*(C0 + C1*z^2);  acc += (ct*z)*tanh(arg)   [f32x2]
// ---------------------------------------------------------------------------
__device__ __forceinline__ void gelu2t(ull a2, ull b2, ull c2, ull C0, ull C1,
                                       ull& acc_t) {
    ull z2; ADD2(z2, a2, b2);
    ull q2; MUL2(q2, z2, z2);
    ull p2; FMA2(p2, C1, q2, C0);
    ull g2; MUL2(g2, z2, p2);
    float glo, ghi;
    asm("mov.b64 {%0,%1}, %2;" : "=f"(glo), "=f"(ghi) : "l"(g2));
    float tlo, thi;
    asm("tanh.approx.f32 %0, %1;" : "=f"(tlo) : "f"(glo));
    asm("tanh.approx.f32 %0, %1;" : "=f"(thi) : "f"(ghi));
    ull th2;
    asm("mov.b64 %0, {%1,%2};" : "=l"(th2) : "f"(tlo), "f"(thi));
    ull w2; MUL2(w2, c2, z2);
    FMA2(acc_t, w2, th2, acc_t);
}

// ---------------------------------------------------------------------------
// Main: out[l,s,t] = sum_i (ct*z)*tanh + Ca[l,s] + Cb[l,t]
// 64 threads, 16x16 tile, 2s x 2t per thread, grid 640. smem ~9KB, high occ.
// ---------------------------------------------------------------------------
#define STRD 68

__global__ void __launch_bounds__(64, 12) main_kernel(float* __restrict__ out) {
    const int l  = blockIdx.z;
    const int s0 = blockIdx.y * 16;
    const int t0 = blockIdx.x * 16;
    const int tid = threadIdx.x;
    const int txx = tid & 7;    // t rows txx, txx+8
    const int tyy = tid >> 3;   // s rows tyy, tyy+8 (0..7? no: tid>>3 in 0..7)

    __shared__ __align__(16) float sA[16][STRD];
    __shared__ __align__(16) float sB[16][STRD];
    __shared__ __align__(16) float sC[64];
    __shared__ float sCa[16], sCb[16];

    if (tid < 16)      sCa[tid]      = g_cab[0][l * SS + s0 + tid];
    else if (tid < 32) sCb[tid - 16] = g_cab[1][l * SS + t0 + tid - 16];

    const float* __restrict__ Abase = &g_ab[0][(l * SS + s0) * HH];
    const float* __restrict__ Bbase = &g_ab[1][(l * SS + t0) * HH];
    const float* __restrict__ Cbase = &g_ct[l * HH];

    ull C0_2, C1_2;
    asm("mov.b64 %0, {%1,%1};" : "=l"(C0_2) : "f"(0.7978845608028654f));
    asm("mov.b64 %0, {%1,%1};" : "=l"(C1_2) : "f"(0.035677408136300125f));

    ull t00 = 0, t01 = 0, t10 = 0, t11 = 0;

    for (int c0 = 0; c0 < HH; c0 += 64) {
        __syncthreads();
        #pragma unroll
        for (int e = tid; e < 256; e += 64) {
            int r = e >> 4, c4 = (e & 15) << 2;
            *(float4*)&sA[r][c4] = *(const float4*)(Abase + r * HH + c0 + c4);
            *(float4*)&sB[r][c4] = *(const float4*)(Bbase + r * HH + c0 + c4);
        }
        if (tid < 16) *(float4*)&sC[tid * 4] = *(const float4*)(Cbase + c0 + tid * 4);
        __syncthreads();

        #pragma unroll 4
        for (int ii = 0; ii < 64; ii += 2) {
            ull a0 = *(const ull*)&sA[tyy][ii];
            ull a1 = *(const ull*)&sA[tyy + 8][ii];
            ull b0 = *(const ull*)&sB[txx][ii];
            ull b1 = *(const ull*)&sB[txx + 8][ii];
            ull cc = *(const ull*)&sC[ii];
            gelu2t(a0, b0, cc, C0_2, C1_2, t00);
            gelu2t(a0, b1, cc, C0_2, C1_2, t01);
            gelu2t(a1, b0, cc, C0_2, C1_2, t10);
            gelu2t(a1, b1, cc, C0_2, C1_2, t11);
        }
    }

    float xlo, xhi;
    float caA = sCa[tyy], caB = sCa[tyy + 8];
    float cbA = sCb[txx], cbB = sCb[txx + 8];
    const int sa = s0 + tyy, sb = s0 + tyy + 8;
    const int ta = t0 + txx, tb = t0 + txx + 8;

    asm("mov.b64 {%0,%1}, %2;" : "=f"(xlo), "=f"(xhi) : "l"(t00));
    out[(l * SS + sa) * SS + ta] = (xlo + xhi) + caA + cbA;
    asm("mov.b64 {%0,%1}, %2;" : "=f"(xlo), "=f"(xhi) : "l"(t01));
    out[(l * SS + sa) * SS + tb] = (xlo + xhi) + caA + cbB;
    asm("mov.b64 {%0,%1}, %2;" : "=f"(xlo), "=f"(xhi) : "l"(t10));
    out[(l * SS + sb) * SS + ta] = (xlo + xhi) + caB + cbA;
    asm("mov.b64 {%0,%1}, %2;" : "=f"(xlo), "=f"(xhi) : "l"(t11));
    out[(l * SS + sb) * SS + tb] = (xlo + xhi) + caB + cbB;
}

// ---------------------------------------------------------------------------
extern "C" void kernel_launch(void* const* d_in, const int* in_sizes, int n_in,
                              void* d_out, int out_size) {
    const float* x    = (const float*)d_in[0];
    const float* Wsrc = (const float*)d_in[1];
    const float* bsrc = (const float*)d_in[2];
    const float* Wtgt = (const float*)d_in[3];
    const float* btgt = (const float*)d_in[4];
    const float* Asrc = (const float*)d_in[5];
    const float* Bsrc = (const float*)d_in[6];
    const float* Atgt = (const float*)d_in[7];
    const float* Btgt = (const float*)d_in[8];
    const float* cls  = (const float*)d_in[9];
    float* out = (float*)d_out;

    prep_kernel  <<<232, 256>>>(x, Wsrc, bsrc, Wtgt, btgt,
                                Asrc, Bsrc, Atgt, Btgt, cls);
    expand_kernel<<<dim3(8, LL, 2), 256>>>();
    main_kernel  <<<dim3(8, 8, LL), 64>>>(out);
}

// round 9
// speedup vs baseline: 3.2681x; 1.1823x over previous
#include <cuda_runtime.h>
#include <math.h>

#define HH 768
#define SS 128
#define LL 10

typedef unsigned long long ull;

// Scratch (no allocation allowed)
__device__ float g_hp[4][2][SS * HH];      // k-split partials of x@W
__device__ float g_u[2][SS * 20];          // x@A   (rl = r*10+l)
__device__ float g_Bt[2 * LL * 2 * HH];    // Bt[mat][l][r][i] = B[mat][(r*H+i)*L + l]
__device__ float g_ct[LL * HH];            // ct[l][i] = 0.5 * classifier[i*L + l]
__device__ float g_ab[2][LL * SS * HH];    // a[l][s][i], b[l][t][i]
__device__ float g_cab[2][LL * SS];        // Ca[l][s] = sum_i ct*a ; Cb[l][t]

// Packed f32x2 ops (sm_100+). ptxas will not auto-emit these.
#define ADD2(o,a,b)   asm("add.rn.f32x2 %0,%1,%2;"    : "=l"(o) : "l"(a), "l"(b))
#define MUL2(o,a,b)   asm("mul.rn.f32x2 %0,%1,%2;"    : "=l"(o) : "l"(a), "l"(b))
#define FMA2(o,a,b,c) asm("fma.rn.f32x2 %0,%1,%2,%3;" : "=l"(o) : "l"(a), "l"(b), "l"(c))

// ---------------------------------------------------------------------------
// Prep kernel, 528 blocks x 256 threads:
//   blocks 0..383   : gemm partials (2 mats x 12 i-tiles x 4 s-tiles x 4 ksplit)
//   blocks 384..511 : u[s][r][l]
//   blocks 512..527 : transposes (Bt, ct)
// ---------------------------------------------------------------------------
__global__ void __launch_bounds__(256) prep_kernel(
        const float* __restrict__ x,
        const float* __restrict__ Wsrc, const float* __restrict__ Wtgt,
        const float* __restrict__ Asrc, const float* __restrict__ Bsrc,
        const float* __restrict__ Atgt, const float* __restrict__ Btgt,
        const float* __restrict__ cls) {
    const int bid = blockIdx.x;
    const int tid = threadIdx.x;

    if (bid < 384) {
        // ---- gemm partial: 32s x 64i tile, k-range 192 (6 chunks of 32) ----
        const int p    = bid & 3;
        const int rest = bid >> 2;
        const int it   = rest % 12;
        const int st   = (rest / 12) % 4;
        const int mat  = rest / 48;
        const float* __restrict__ Wm = mat ? Wtgt : Wsrc;
        const int i0 = it * 64;
        const int s0 = st * 32;
        const int kb = p * 192;

        __shared__ float sX[32][34];                  // [k][s], pad 34: 8B-aligned
        __shared__ __align__(16) float sW[32][64];    // [k][i]

        const int tx  = tid & 15;       // i (4 each)
        const int ty  = tid >> 4;       // s (2 each)
        const int kx  = tid & 31;       // staging: k lane
        const int sw  = tid >> 5;       // staging: s base (rows sw+8j)
        const int kkw = tid >> 4;       // staging: W row
        const int iw  = (tid & 15) * 4; // staging: W col

        ull acc00 = 0, acc01 = 0, acc10 = 0, acc11 = 0;

        float px[4]; float4 pw0, pw1;
        // prefetch chunk 0
        #pragma unroll
        for (int j = 0; j < 4; j++)
            px[j] = x[(s0 + sw + 8 * j) * HH + kb + kx];
        pw0 = *(const float4*)&Wm[(kb + kkw) * HH + i0 + iw];
        pw1 = *(const float4*)&Wm[(kb + 16 + kkw) * HH + i0 + iw];

        for (int c = 0; c < 6; c++) {
            __syncthreads();
            #pragma unroll
            for (int j = 0; j < 4; j++) sX[kx][sw + 8 * j] = px[j];
            *(float4*)&sW[kkw][iw]      = pw0;
            *(float4*)&sW[kkw + 16][iw] = pw1;
            __syncthreads();
            if (c < 5) {
                const int k0 = kb + (c + 1) * 32;
                #pragma unroll
                for (int j = 0; j < 4; j++)
                    px[j] = x[(s0 + sw + 8 * j) * HH + k0 + kx];
                pw0 = *(const float4*)&Wm[(k0 + kkw) * HH + i0 + iw];
                pw1 = *(const float4*)&Wm[(k0 + 16 + kkw) * HH + i0 + iw];
            }
            #pragma unroll
            for (int kk = 0; kk < 32; kk++) {
                float2 a2 = *(const float2*)&sX[kk][ty * 2];
                ull b01 = *(const ull*)&sW[kk][tx * 4];
                ull b23 = *(const ull*)&sW[kk][tx * 4 + 2];
                ull a0d, a1d;
                asm("mov.b64 %0,{%1,%1};" : "=l"(a0d) : "f"(a2.x));
                asm("mov.b64 %0,{%1,%1};" : "=l"(a1d) : "f"(a2.y));
                FMA2(acc00, a0d, b01, acc00);
                FMA2(acc01, a0d, b23, acc01);
                FMA2(acc10, a1d, b01, acc10);
                FMA2(acc11, a1d, b23, acc11);
            }
        }
        float v[2][4];
        asm("mov.b64 {%0,%1}, %2;" : "=f"(v[0][0]), "=f"(v[0][1]) : "l"(acc00));
        asm("mov.b64 {%0,%1}, %2;" : "=f"(v[0][2]), "=f"(v[0][3]) : "l"(acc01));
        asm("mov.b64 {%0,%1}, %2;" : "=f"(v[1][0]), "=f"(v[1][1]) : "l"(acc10));
        asm("mov.b64 {%0,%1}, %2;" : "=f"(v[1][2]), "=f"(v[1][3]) : "l"(acc11));
        #pragma unroll
        for (int i = 0; i < 2; i++)
            #pragma unroll
            for (int j = 0; j < 4; j++) {
                int s  = s0 + ty * 2 + i;
                int ii = i0 + tx * 4 + j;
                g_hp[p][mat][s * HH + ii] = v[i][j];
            }
    } else if (bid < 512) {
        // ---- u[s][r][l] = sum_h x[s,h]*A[h,r,l], 4-way k-split ----
        __shared__ float sx[HH];
        __shared__ float spart[4][40];
        const int s = bid - 384;
        for (int e = tid; e < HH; e += 256) sx[e] = x[s * HH + e];
        __syncthreads();
        const int seg = tid >> 6;
        const int j   = tid & 63;
        if (j < 40) {
            const int mat = j / 20, rl = j % 20;
            const float* __restrict__ A = mat ? Atgt : Asrc;
            float acc = 0.f;
            const int h0 = seg * 192;
            #pragma unroll 8
            for (int h = h0; h < h0 + 192; h++)
                acc = fmaf(sx[h], A[h * 20 + rl], acc);
            spart[seg][j] = acc;
        }
        __syncthreads();
        if (tid < 40) {
            float vv = spart[0][tid] + spart[1][tid] + spart[2][tid] + spart[3][tid];
            g_u[tid / 20][s * 20 + tid % 20] = vv;
        }
    } else {
        // ---- transposes: Bt and ct ----
        const int idx0 = (bid - 512) * 256 + tid;
        for (int n = idx0; n < 2 * LL * 2 * HH; n += 16 * 256) {
            int i   = n % HH;
            int rem = n / HH;
            int r   = rem % 2;
            int l   = (rem / 2) % LL;
            int mat = rem / (2 * LL);
            const float* __restrict__ Bm = mat ? Btgt : Bsrc;
            g_Bt[((mat * LL + l) * 2 + r) * HH + i] = Bm[(r * HH + i) * LL + l];
        }
        for (int n = idx0; n < LL * HH; n += 16 * 256) {
            int i = n % HH, l = n / HH;
            g_ct[l * HH + i] = 0.5f * cls[i * LL + l];
        }
    }
}

// ---------------------------------------------------------------------------
// Expand kernel: ab = (sum_p hp[p]) + bias + u0*Bt0 + u1*Bt1 ;
//                Ca/Cb = sum_i ct*ab   (rank-1 part of the gelu identity)
// grid (8 s-chunks, LL, 2 mats) = 160 blocks, 256 threads.
// ---------------------------------------------------------------------------
__global__ void __launch_bounds__(256) expand_kernel(
        const float* __restrict__ bsrc, const float* __restrict__ btgt) {
    const int mat = blockIdx.z;
    const int l   = blockIdx.y;
    const int s0  = blockIdx.x * 16;
    const int tid = threadIdx.x;
    const float* __restrict__ bm = mat ? btgt : bsrc;

    __shared__ __align__(16) float sBt0[HH], sBt1[HH], sCt[HH], sBias[HH];
    __shared__ float su[16][2];

    for (int e = tid; e < HH; e += 256) {
        sBt0[e]  = g_Bt[((mat * LL + l) * 2 + 0) * HH + e];
        sBt1[e]  = g_Bt[((mat * LL + l) * 2 + 1) * HH + e];
        sCt[e]   = g_ct[l * HH + e];
        sBias[e] = bm[e];
    }
    if (tid < 32) {
        int si = tid >> 1, r = tid & 1;
        su[si][r] = g_u[mat][(s0 + si) * 20 + r * 10 + l];
    }
    __syncthreads();

    const int row    = tid >> 4;
    const int lane16 = tid & 15;
    const float u0 = su[row][0], u1 = su[row][1];
    const int hoff = (s0 + row) * HH;
    float* __restrict__ orow = &g_ab[mat][(l * SS + s0 + row) * HH];

    float ca = 0.f;
    #pragma unroll
    for (int j = 0; j < 12; j++) {
        int i4 = lane16 * 4 + j * 64;
        float4 h0 = *(const float4*)&g_hp[0][mat][hoff + i4];
        float4 h1 = *(const float4*)&g_hp[1][mat][hoff + i4];
        float4 h2 = *(const float4*)&g_hp[2][mat][hoff + i4];
        float4 h3 = *(const float4*)&g_hp[3][mat][hoff + i4];
        float4 bb = *(const float4*)&sBias[i4];
        float4 q0 = *(const float4*)&sBt0[i4];
        float4 q1 = *(const float4*)&sBt1[i4];
        float4 c4 = *(const float4*)&sCt[i4];
        float4 v;
        v.x = ((h0.x + h1.x) + (h2.x + h3.x)) + bb.x;
        v.y = ((h0.y + h1.y) + (h2.y + h3.y)) + bb.y;
        v.z = ((h0.z + h1.z) + (h2.z + h3.z)) + bb.z;
        v.w = ((h0.w + h1.w) + (h2.w + h3.w)) + bb.w;
        v.x = fmaf(u1, q1.x, fmaf(u0, q0.x, v.x));
        v.y = fmaf(u1, q1.y, fmaf(u0, q0.y, v.y));
        v.z = fmaf(u1, q1.z, fmaf(u0, q0.z, v.z));
        v.w = fmaf(u1, q1.w, fmaf(u0, q0.w, v.w));
        *(float4*)&orow[i4] = v;
        ca = fmaf(c4.x, v.x, ca); ca = fmaf(c4.y, v.y, ca);
        ca = fmaf(c4.z, v.z, ca); ca = fmaf(c4.w, v.w, ca);
    }
    #pragma unroll
    for (int o = 8; o; o >>= 1) ca += __shfl_xor_sync(0xffffffffu, ca, o, 16);
    if (lane16 == 0) g_cab[mat][l * SS + s0 + row] = ca;
}

// ---------------------------------------------------------------------------
// gelu pair (tanh-only accumulator; the Sum(w) part is rank-1 -> Ca+Cb):
//   z = a+b;  arg = z*(C0 + C1*z^2);  acc += (ct*z)*tanh(arg)   [f32x2]
// ---------------------------------------------------------------------------
__device__ __forceinline__ void gelu2t(ull a2, ull b2, ull c2, ull C0, ull C1,
                                       ull& acc_t) {
    ull z2; ADD2(z2, a2, b2);
    ull q2; MUL2(q2, z2, z2);
    ull p2; FMA2(p2, C1, q2, C0);
    ull g2; MUL2(g2, z2, p2);
    float glo, ghi;
    asm("mov.b64 {%0,%1}, %2;" : "=f"(glo), "=f"(ghi) : "l"(g2));
    float tlo, thi;
    asm("tanh.approx.f32 %0, %1;" : "=f"(tlo) : "f"(glo));
    asm("tanh.approx.f32 %0, %1;" : "=f"(thi) : "f"(ghi));
    ull th2;
    asm("mov.b64 %0, {%1,%2};" : "=l"(th2) : "f"(tlo), "f"(thi));
    ull w2; MUL2(w2, c2, z2);
    FMA2(acc_t, w2, th2, acc_t);
}

// ---------------------------------------------------------------------------
// Main: out[l,s,t] = sum_i (ct*z)*tanh + Ca[l,s] + Cb[l,t]
// 64 threads, 16x16 tile, 2s x 2t per thread, grid 640.  (at MUFU floor)
// ---------------------------------------------------------------------------
#define STRD 68

__global__ void __launch_bounds__(64, 12) main_kernel(float* __restrict__ out) {
    const int l  = blockIdx.z;
    const int s0 = blockIdx.y * 16;
    const int t0 = blockIdx.x * 16;
    const int tid = threadIdx.x;
    const int txx = tid & 7;
    const int tyy = tid >> 3;

    __shared__ __align__(16) float sA[16][STRD];
    __shared__ __align__(16) float sB[16][STRD];
    __shared__ __align__(16) float sC[64];
    __shared__ float sCa[16], sCb[16];

    if (tid < 16)      sCa[tid]      = g_cab[0][l * SS + s0 + tid];
    else if (tid < 32) sCb[tid - 16] = g_cab[1][l * SS + t0 + tid - 16];

    const float* __restrict__ Abase = &g_ab[0][(l * SS + s0) * HH];
    const float* __restrict__ Bbase = &g_ab[1][(l * SS + t0) * HH];
    const float* __restrict__ Cbase = &g_ct[l * HH];

    ull C0_2, C1_2;
    asm("mov.b64 %0, {%1,%1};" : "=l"(C0_2) : "f"(0.7978845608028654f));
    asm("mov.b64 %0, {%1,%1};" : "=l"(C1_2) : "f"(0.035677408136300125f));

    ull t00 = 0, t01 = 0, t10 = 0, t11 = 0;

    for (int c0 = 0; c0 < HH; c0 += 64) {
        __syncthreads();
        #pragma unroll
        for (int e = tid; e < 256; e += 64) {
            int r = e >> 4, c4 = (e & 15) << 2;
            *(float4*)&sA[r][c4] = *(const float4*)(Abase + r * HH + c0 + c4);
            *(float4*)&sB[r][c4] = *(const float4*)(Bbase + r * HH + c0 + c4);
        }
        if (tid < 16) *(float4*)&sC[tid * 4] = *(const float4*)(Cbase + c0 + tid * 4);
        __syncthreads();

        #pragma unroll 4
        for (int ii = 0; ii < 64; ii += 2) {
            ull a0 = *(const ull*)&sA[tyy][ii];
            ull a1 = *(const ull*)&sA[tyy + 8][ii];
            ull b0 = *(const ull*)&sB[txx][ii];
            ull b1 = *(const ull*)&sB[txx + 8][ii];
            ull cc = *(const ull*)&sC[ii];
            gelu2t(a0, b0, cc, C0_2, C1_2, t00);
            gelu2t(a0, b1, cc, C0_2, C1_2, t01);
            gelu2t(a1, b0, cc, C0_2, C1_2, t10);
            gelu2t(a1, b1, cc, C0_2, C1_2, t11);
        }
    }

    float xlo, xhi;
    float caA = sCa[tyy], caB = sCa[tyy + 8];
    float cbA = sCb[txx], cbB = sCb[txx + 8];
    const int sa = s0 + tyy, sb = s0 + tyy + 8;
    const int ta = t0 + txx, tb = t0 + txx + 8;

    asm("mov.b64 {%0,%1}, %2;" : "=f"(xlo), "=f"(xhi) : "l"(t00));
    out[(l * SS + sa) * SS + ta] = (xlo + xhi) + caA + cbA;
    asm("mov.b64 {%0,%1}, %2;" : "=f"(xlo), "=f"(xhi) : "l"(t01));
    out[(l * SS + sa) * SS + tb] = (xlo + xhi) + caA + cbB;
    asm("mov.b64 {%0,%1}, %2;" : "=f"(xlo), "=f"(xhi) : "l"(t10));
    out[(l * SS + sb) * SS + ta] = (xlo + xhi) + caB + cbA;
    asm("mov.b64 {%0,%1}, %2;" : "=f"(xlo), "=f"(xhi) : "l"(t11));
    out[(l * SS + sb) * SS + tb] = (xlo + xhi) + caB + cbB;
}

// ---------------------------------------------------------------------------
extern "C" void kernel_launch(void* const* d_in, const int* in_sizes, int n_in,
                              void* d_out, int out_size) {
    const float* x    = (const float*)d_in[0];
    const float* Wsrc = (const float*)d_in[1];
    const float* bsrc = (const float*)d_in[2];
    const float* Wtgt = (const float*)d_in[3];
    const float* btgt = (const float*)d_in[4];
    const float* Asrc = (const float*)d_in[5];
    const float* Bsrc = (const float*)d_in[6];
    const float* Atgt = (const float*)d_in[7];
    const float* Btgt = (const float*)d_in[8];
    const float* cls  = (const float*)d_in[9];
    float* out = (float*)d_out;

    prep_kernel  <<<528, 256>>>(x, Wsrc, Wtgt, Asrc, Bsrc, Atgt, Btgt, cls);
    expand_kernel<<<dim3(8, LL, 2), 256>>>(bsrc, btgt);
    main_kernel  <<<dim3(8, 8, LL), 64>>>(out);
}